// round 4
// baseline (speedup 1.0000x reference)
#include <cuda_runtime.h>

// out[b, t, f] = (t == (int)((1.0f - x[b,f]) * 100.0f)) ? 1.0f : 0.0f
// B=2048, T=100, F=1024. Output 839 MB -> pure HBM-store-bound.
// R4: TCHUNK 25 -> 10 (20480 blocks, ~17 waves) to shrink wave-boundary
//     DRAM drain bubbles. x re-reads stay L2-resident (8 MB << 126 MB L2).

#define B 2048
#define T 100
#define TCHUNK 10
#define NCHUNK (T / TCHUNK)   // 10
#define F 1024
#define F4 (F / 4)            // 256

__global__ __launch_bounds__(256, 8)
void spike_latency_kernel(const float4* __restrict__ x, float4* __restrict__ out) {
    int gtid = blockIdx.x * blockDim.x + threadIdx.x;   // 0 .. B*F4-1
    int b  = gtid >> 8;        // / F4
    int f4 = gtid & (F4 - 1);  // % F4
    int t0 = blockIdx.y * TCHUNK;

    float4 xv = __ldg(x + gtid);
    int s0 = (int)((1.0f - xv.x) * 100.0f);
    int s1 = (int)((1.0f - xv.y) * 100.0f);
    int s2 = (int)((1.0f - xv.z) * 100.0f);
    int s3 = (int)((1.0f - xv.w) * 100.0f);

    float4* po = out + (size_t)b * (T * F4) + (size_t)t0 * F4 + f4;

#pragma unroll
    for (int i = 0; i < TCHUNK; i++) {
        int t = t0 + i;
        float4 v;
        v.x = (t == s0) ? 1.0f : 0.0f;
        v.y = (t == s1) ? 1.0f : 0.0f;
        v.z = (t == s2) ? 1.0f : 0.0f;
        v.w = (t == s3) ? 1.0f : 0.0f;
        __stcs(po + (size_t)i * F4, v);   // evict-first streaming store
    }
}

extern "C" void kernel_launch(void* const* d_in, const int* in_sizes, int n_in,
                              void* d_out, int out_size) {
    const float4* x = (const float4*)d_in[0];
    float4* out = (float4*)d_out;
    dim3 grid(B * F4 / 256, NCHUNK);   // (2048, 10)
    spike_latency_kernel<<<grid, 256>>>(x, out);
}

// round 5
// speedup vs baseline: 1.0164x; 1.0164x over previous
#include <cuda_runtime.h>

// out[b, t, f] = (t == (int)((1.0f - x[b,f]) * 100.0f)) ? 1.0f : 0.0f
// B=2048, T=100, F=1024. Output 839 MB -> pure HBM-store-bound.
// R5: TCHUNK 10 -> 5 (40960 blocks, ~35 waves) - final wave-grain probe.
//     x re-reads stay L2-resident (8 MB << 126 MB L2).

#define B 2048
#define T 100
#define TCHUNK 5
#define NCHUNK (T / TCHUNK)   // 20
#define F 1024
#define F4 (F / 4)            // 256

__global__ __launch_bounds__(256, 8)
void spike_latency_kernel(const float4* __restrict__ x, float4* __restrict__ out) {
    int gtid = blockIdx.x * blockDim.x + threadIdx.x;   // 0 .. B*F4-1
    int b  = gtid >> 8;        // / F4
    int f4 = gtid & (F4 - 1);  // % F4
    int t0 = blockIdx.y * TCHUNK;

    float4 xv = __ldg(x + gtid);
    int s0 = (int)((1.0f - xv.x) * 100.0f);
    int s1 = (int)((1.0f - xv.y) * 100.0f);
    int s2 = (int)((1.0f - xv.z) * 100.0f);
    int s3 = (int)((1.0f - xv.w) * 100.0f);

    float4* po = out + (size_t)b * (T * F4) + (size_t)t0 * F4 + f4;

#pragma unroll
    for (int i = 0; i < TCHUNK; i++) {
        int t = t0 + i;
        float4 v;
        v.x = (t == s0) ? 1.0f : 0.0f;
        v.y = (t == s1) ? 1.0f : 0.0f;
        v.z = (t == s2) ? 1.0f : 0.0f;
        v.w = (t == s3) ? 1.0f : 0.0f;
        __stcs(po + (size_t)i * F4, v);   // evict-first streaming store
    }
}

extern "C" void kernel_launch(void* const* d_in, const int* in_sizes, int n_in,
                              void* d_out, int out_size) {
    const float4* x = (const float4*)d_in[0];
    float4* out = (float4*)d_out;
    dim3 grid(B * F4 / 256, NCHUNK);   // (2048, 20)
    spike_latency_kernel<<<grid, 256>>>(x, out);
}